// round 15
// baseline (speedup 1.0000x reference)
#include <cuda_runtime.h>
#include <math.h>

#define NSMP   256000        // = 512 * 500
#define N1     512
#define N2     500
#define NBATCH 4
#define NFR    500
#define NBK    64
#define NFQ    128001
#define NCH    10
#define CHF    50

// ---------------- scratch ----------------
__device__ float2 g_u[2][N1 * N2];      // 4 MB working buffer
__device__ float2 g_Ht2[2][N1 * N2];    // transposed filter, paired: [s][k1*500+k2] = {H[2s],H[2s+1]}
__device__ float  g_part[NCH][NBATCH][NBK];

// ---------------- helpers ----------------
__device__ __forceinline__ float2 c_add(float2 a, float2 b){ return make_float2(a.x+b.x, a.y+b.y); }
__device__ __forceinline__ float2 c_sub(float2 a, float2 b){ return make_float2(a.x-b.x, a.y-b.y); }
__device__ __forceinline__ float2 cxm(float2 a, float2 b){
    return make_float2(a.x*b.x - a.y*b.y, a.x*b.y + a.y*b.x);
}

template<int R, bool INV>
__device__ __forceinline__ void butterfly(float2* v) {
    const float s = INV ? 1.f : -1.f;
    if constexpr (R == 4) {
        float2 t0 = c_add(v[0], v[2]), t1 = c_sub(v[0], v[2]);
        float2 t2 = c_add(v[1], v[3]), t3 = c_sub(v[1], v[3]);
        float2 it3 = make_float2(-s * t3.y, s * t3.x);
        v[0] = c_add(t0, t2); v[2] = c_sub(t0, t2);
        v[1] = c_add(t1, it3); v[3] = c_sub(t1, it3);
    } else if constexpr (R == 5) {
        const float c1 = 0.30901699437494742f, c2 = -0.80901699437494745f;
        const float s1 = 0.95105651629515357f, s2 =  0.58778525229247312f;
        float2 t1 = c_add(v[1], v[4]), t2 = c_add(v[2], v[3]);
        float2 t3 = c_sub(v[1], v[4]), t4 = c_sub(v[2], v[3]);
        float2 x0 = v[0];
        float2 m1 = make_float2(x0.x + c1*t1.x + c2*t2.x, x0.y + c1*t1.y + c2*t2.y);
        float2 m2 = make_float2(x0.x + c2*t1.x + c1*t2.x, x0.y + c2*t1.y + c1*t2.y);
        float2 u1 = make_float2(s1*t3.x + s2*t4.x, s1*t3.y + s2*t4.y);
        float2 u2 = make_float2(s2*t3.x - s1*t4.x, s2*t3.y - s1*t4.y);
        float2 iu1 = make_float2(-s*u1.y, s*u1.x);
        float2 iu2 = make_float2(-s*u2.y, s*u2.x);
        v[0] = make_float2(x0.x + t1.x + t2.x, x0.y + t1.y + t2.y);
        v[1] = c_add(m1, iu1); v[4] = c_sub(m1, iu1);
        v[2] = c_add(m2, iu2); v[3] = c_sub(m2, iu2);
    }
}

template<bool INV>
__device__ __forceinline__ void bfly8(float2* v) {
    float2 u0[4] = { v[0], v[2], v[4], v[6] };
    float2 u1[4] = { v[1], v[3], v[5], v[7] };
    butterfly<4, INV>(u0);
    butterfly<4, INV>(u1);
    const float h  = 0.70710678118654752f;
    const float si = INV ? 1.f : -1.f;
    float2 t0 = u1[0];
    float2 t1 = make_float2(h*(u1[1].x - si*u1[1].y), h*(si*u1[1].x + u1[1].y));
    float2 t2 = make_float2(-si*u1[2].y, si*u1[2].x);
    float2 t3 = make_float2(h*(-u1[3].x - si*u1[3].y), h*(si*u1[3].x - u1[3].y));
    v[0] = c_add(u0[0], t0); v[4] = c_sub(u0[0], t0);
    v[1] = c_add(u0[1], t1); v[5] = c_sub(u0[1], t1);
    v[2] = c_add(u0[2], t2); v[6] = c_sub(u0[2], t2);
    v[3] = c_add(u0[3], t3); v[7] = c_sub(u0[3], t3);
}

// one sincosf + power chain: multiply v[1..4] by w^r
__device__ __forceinline__ void tw5(float base, float2* v) {
    float sn, cs; __sincosf(base, &sn, &cs);
    float2 w1 = make_float2(cs, sn);
    float2 w2 = cxm(w1, w1);
    float2 w3 = cxm(w2, w1);
    float2 w4 = cxm(w2, w2);
    v[1] = cxm(v[1], w1); v[2] = cxm(v[2], w2);
    v[3] = cxm(v[3], w3); v[4] = cxm(v[4], w4);
}

// one sincosf + power chain: multiply v[1..7] by w^r
__device__ __forceinline__ void tw8(float base, float2* v) {
    float sn, cs; __sincosf(base, &sn, &cs);
    float2 w1 = make_float2(cs, sn);
    float2 w2 = cxm(w1, w1);
    float2 w3 = cxm(w2, w1);
    float2 w4 = cxm(w2, w2);
    float2 w5 = cxm(w4, w1);
    float2 w6 = cxm(w3, w3);
    float2 w7 = cxm(w3, w4);
    v[1] = cxm(v[1], w1); v[2] = cxm(v[2], w2); v[3] = cxm(v[3], w3);
    v[4] = cxm(v[4], w4); v[5] = cxm(v[5], w5); v[6] = cxm(v[6], w6);
    v[7] = cxm(v[7], w7);
}

// radix-5 Stockham stage body (caller guards t<100)
template<bool INV>
__device__ __forceinline__ void stage5(const float2* __restrict__ src, float2* __restrict__ dst,
                                       int t, int m, int Ns, float base) {
    float2 v[5];
#pragma unroll
    for (int r = 0; r < 5; r++) v[r] = src[t + 100*r];
    tw5(base, v);
    butterfly<5, INV>(v);
    int db = (t/Ns)*(Ns*5) + m;
#pragma unroll
    for (int r = 0; r < 5; r++) dst[db + Ns*r] = v[r];
}

#define BROW() asm volatile("bar.sync %0, 128;" :: "r"(half + 1) : "memory")

// ---------------- partial mean-magnitude (closed-form frame weights) ----------------
__global__ void k_mm_part(const float* __restrict__ mag) {
    int c = blockIdx.x, b = blockIdx.y;
    int t = threadIdx.x;    // 64
    __shared__ float sw[CHF];
    if (t < CHF) {
        int f = c*CHF + t;
        const double s = 499.0/255999.0;
        long long a1 = ((long long)f*255999LL + 498LL)/499LL;
        long long b1 = ((long long)(f+1)*255999LL + 498LL)/499LL - 1LL;
        if (b1 > 255999LL) b1 = 255999LL;
        double cnt1 = (double)(b1 - a1 + 1);
        double si1  = 0.5*(double)(a1 + b1)*cnt1;
        double sum  = cnt1*(double)(1 + f) - s*si1;
        if (f >= 1) {
            long long a2 = ((long long)(f-1)*255999LL + 498LL)/499LL;
            long long b2 = a1 - 1LL;
            if (b2 >= a2) {
                double cnt2 = (double)(b2 - a2 + 1);
                double si2  = 0.5*(double)(a2 + b2)*cnt2;
                sum += s*si2 - (double)(f-1)*cnt2;
            }
        }
        sw[t] = (float)(sum/256000.0);
    }
    __syncthreads();
    float acc = 0.f;
    const float* mp = mag + (b*NFR + c*CHF)*NBK + t;
#pragma unroll 10
    for (int f = 0; f < CHF; f++) acc += sw[f]*mp[f*NBK];
    g_part[c][b][t] = acc;
}

// ---------------- filter response over frequencies, dual scatter-write to transposed table ----------------
__global__ void __launch_bounds__(128) k_filter_Ht() {
    // PDL: overlap launch with k_mm_part tail; block before reading g_part
    cudaGridDependencySynchronize();

    __shared__ float smm[NBATCH*NBK];
    int t = threadIdx.x;
    for (int i = t; i < NBATCH*NBK; i += 128) {
        float a = 0.f;
        const float* p = (const float*)g_part;
#pragma unroll
        for (int c = 0; c < NCH; c++) a += p[c*256 + i];
        smm[i] = a;
    }
    __syncthreads();

    int f = blockIdx.x*128 + t;
    if (f >= NFQ) return;

    const float la = 2.9957322735539909f;          // ln(20)
    const float d  = 0.10019346708895288f;         // (ln(11025)-ln(20))/63
    const float C2 = 0.98012272f;                  // exp(-2 d^2)
    const float C8 = 0.92283040f;                  // exp(-8 d^2)
    const float G4 = 0.85161593f;                  // exp(-16 d^2)

    float freq = (float)f * (22050.0f/256000.0f);
    float xp = __logf(freq + 1e-7f) - la;

    float te = __expf(-2.f*xp*xp);
    float E  = __expf(4.f*d*xp);
    float to = te*E*C2;
    float E2 = E*E;
    float Re = E2*C8;
    float Ro = Re*C8;

    float sum = 0.f, a0 = 0.f, a1 = 0.f, a2 = 0.f, a3 = 0.f;
#pragma unroll
    for (int q = 0; q < 64; q += 2) {
        sum += te + to;
        a0 += te*smm[q]       + to*smm[q+1];
        a1 += te*smm[64+q]    + to*smm[65+q];
        a2 += te*smm[128+q]   + to*smm[129+q];
        a3 += te*smm[192+q]   + to*smm[193+q];
        te *= Re; Re *= G4;
        to *= Ro; Ro *= G4;
    }
    float inv = 1.f/(sum + 1e-7f);
    float2 h01 = make_float2(a0*inv, a1*inv);
    float2 h23 = make_float2(a2*inv, a3*inv);

    int idxA = (f & 511)*N2 + (f >> 9);
    g_Ht2[0][idxA] = h01;
    g_Ht2[1][idxA] = h23;
    if (f > 0 && f < 128000) {
        int kb = 256000 - f;
        int idxB = (kb & 511)*N2 + (kb >> 9);
        g_Ht2[0][idxB] = h01;
        g_Ht2[1][idxB] = h23;
    }
}

// ---------------- pass 1: float4 staging + FFT-512 per column + cross twiddle ----------------
__global__ void __launch_bounds__(512) k_p1f(const float* __restrict__ noise) {
    __shared__ float2 smA[8][516];
    __shared__ float2 smB[8][516];
    float2* stage = (float2*)smB;        // staging aliases smB (dead until stage 2)
    int tid = threadIdx.x;
    int c = tid & 7, j = tid >> 3;       // j in [0,64)
    int bx = blockIdx.x;
    int n2 = bx*8 + c;
    bool val = (n2 < N2);
    int s = blockIdx.y;
    const float* n0r = noise + 2*s*NSMP;
    const float* n1r = noise + (2*s+1)*NSMP;

    // cooperative float4 staging: stage[row*8+col] = (n0[row,col], n1[row,col])
#pragma unroll
    for (int q = tid; q < 1024; q += 512) {
        int row = q >> 1, h = q & 1;
        int cb = bx*8 + (h << 2);
        float2* dst = stage + row*8 + (h << 2);
        if (cb + 3 < N2) {
            float4 a = *(const float4*)(n0r + row*N2 + cb);
            float4 b = *(const float4*)(n1r + row*N2 + cb);
            dst[0] = make_float2(a.x, b.x);
            dst[1] = make_float2(a.y, b.y);
            dst[2] = make_float2(a.z, b.z);
            dst[3] = make_float2(a.w, b.w);
        } else {
#pragma unroll
            for (int i = 0; i < 4; i++) {
                int cc = cb + i;
                dst[i] = (cc < N2) ? make_float2(n0r[row*N2 + cc], n1r[row*N2 + cc])
                                   : make_float2(0.f, 0.f);
            }
        }
    }
    __syncthreads();

    float2 v[8];
#pragma unroll
    for (int r = 0; r < 8; r++) v[r] = stage[(j + (r << 6))*8 + c];
    __syncthreads();                     // all stage reads done before smA... (smB reuse safe after s2 barrier)
    bfly8<false>(v);
#pragma unroll
    for (int r = 0; r < 8; r++) smA[c][j*8 + r] = v[r];
    __syncthreads();
    {
#pragma unroll
        for (int r = 0; r < 8; r++) v[r] = smA[c][j + 64*r];
        int m = j & 7;
        tw8(-6.2831853071795864f/64.f * (float)m, v);
        bfly8<false>(v);
        int db = (j >> 3)*64 + m;
#pragma unroll
        for (int r = 0; r < 8; r++) smB[c][db + 8*r] = v[r];
    }
    __syncthreads();
    {
#pragma unroll
        for (int r = 0; r < 8; r++) v[r] = smB[c][j + 64*r];
        tw8(-6.2831853071795864f/512.f * (float)j, v);
        bfly8<false>(v);
        if (val) {
            float cb2 = -6.2831853071795864f/256000.f * (float)n2;
            float snj, csj; __sincosf(cb2*(float)j, &snj, &csj);
            float snW, csW; __sincosf(cb2*64.f, &snW, &csW);
            float2 wk = make_float2(csj, snj);
            float2 W  = make_float2(csW, snW);
            float2* u = g_u[s];
#pragma unroll
            for (int r = 0; r < 8; r++) {
                int k1 = j + 64*r;
                u[k1*N2 + n2] = cxm(v[r], wk);
                wk = cxm(wk, W);
            }
        }
    }
}

// ---------------- fused middle: fwd FFT-500 + spectral filter (coalesced Ht2) + inv FFT-500 ----------------
__global__ void __launch_bounds__(256) k_pMid() {
    __shared__ float2 sA[2][N2], sB[2][N2];
    int tid = threadIdx.x;
    int half = tid >> 7, t = tid & 127;
    int p = blockIdx.x;                  // 0..255
    int s = blockIdx.y;
    int ra = (p == 0) ? 0   : p;
    int rb = (p == 0) ? 256 : 512 - p;
    int myrow = half ? rb : ra;
    float2* A = sA[half];
    float2* B = sB[half];

    // PDL: overlap launch with p1f tail; block before first dependent read
    cudaGridDependencySynchronize();

    // fwd s1: radix-4, Ns=1 — read g_u directly
    {
        const float2* src = g_u[s] + myrow*N2;
        if (t < 125) {
            float2 v[4];
#pragma unroll
            for (int r = 0; r < 4; r++) v[r] = src[t + 125*r];
            butterfly<4, false>(v);
#pragma unroll
            for (int r = 0; r < 4; r++) A[t*4 + r] = v[r];
        }
    }
    BROW();
    if (t < 100) stage5<false>(A, B, t, t & 3,  4,  -6.2831853071795864f/20.f  * (float)(t & 3));
    BROW();
    if (t < 100) stage5<false>(B, A, t, t % 20, 20, -6.2831853071795864f/100.f * (float)(t % 20));
    BROW();
    if (t < 100) stage5<false>(A, B, t, t,      100,-6.2831853071795864f/500.f * (float)t);
    __syncthreads();    // spectrum in sB (both halves)

    // spectral filter fused into inverse s1 (radix-4, Ns=1): sB -> sA
    {
        const float2* Hp = g_Ht2[s] + myrow*N2;   // coalesced: adjacent lanes adjacent k2
        if (t < 125) {
            float2 v[4];
#pragma unroll
            for (int r = 0; r < 4; r++) {
                int k2 = t + 125*r;
                float2 zk = B[k2];
                float2 zn;
                if (p == 0) {
                    if (!half) zn = sB[0][k2 ? N2 - k2 : 0];
                    else       zn = sB[1][N2 - 1 - k2];
                } else {
                    zn = sB[1 - half][N2 - 1 - k2];
                }
                float2 h = Hp[k2];
                float X0r = 0.5f*(zk.x + zn.x), X0i = 0.5f*(zk.y - zn.y);
                float X1r = 0.5f*(zk.y + zn.y), X1i = -0.5f*(zk.x - zn.x);
                v[r] = make_float2(h.x*X0r - h.y*X1i, h.x*X0i + h.y*X1r);
            }
            butterfly<4, true>(v);
#pragma unroll
            for (int r = 0; r < 4; r++) A[t*4 + r] = v[r];
        }
    }
    __syncthreads();    // cross-half sB reads must finish before inv writes sB

    if (t < 100) stage5<true>(A, B, t, t & 3,  4,  6.2831853071795864f/20.f  * (float)(t & 3));
    BROW();
    if (t < 100) stage5<true>(B, A, t, t % 20, 20, 6.2831853071795864f/100.f * (float)(t % 20));
    BROW();
    // inv s4 (Ns=100) fused with cross-twiddle + store
    if (t < 100) {
        float2 v[5];
#pragma unroll
        for (int r = 0; r < 5; r++) v[r] = A[t + 100*r];
        tw5(6.2831853071795864f/500.f * (float)t, v);
        butterfly<5, true>(v);
        float cb = 6.2831853071795864f/256000.f * (float)myrow;
        float snt, cst; __sincosf(cb*(float)t,   &snt, &cst);
        float snW, csW; __sincosf(cb*100.f,      &snW, &csW);
        float2 wk = make_float2(cst, snt);
        float2 W  = make_float2(csW, snW);
        float2* dst = g_u[s] + myrow*N2;
#pragma unroll
        for (int r = 0; r < 5; r++) {
            dst[t + 100*r] = cxm(v[r], wk);
            wk = cxm(wk, W);
        }
    }
}

// ---------------- pass B: float4 staging + iFFT-512 per column + scale + unpack ----------------
__global__ void __launch_bounds__(512) k_pBi(float* __restrict__ out) {
    __shared__ float2 smA[8][516];
    __shared__ float2 smB[8][516];
    float2* stage = (float2*)smB;
    int tid = threadIdx.x;
    int c = tid & 7, j = tid >> 3;
    int bx = blockIdx.x;
    int n2 = bx*8 + c;
    bool val = (n2 < N2);
    int s = blockIdx.y;
    const float2* u = g_u[s];

    // PDL: overlap launch with pMid tail; block before first dependent read
    cudaGridDependencySynchronize();

    // cooperative float4 staging of the g_u tile: stage[row*8+col] = u[row*500 + bx*8+col]
#pragma unroll
    for (int q = tid; q < 2048; q += 512) {
        int row = q >> 2, quad = q & 3;
        int cb = bx*8 + (quad << 1);
        float2* dst = stage + row*8 + (quad << 1);
        if (cb + 1 < N2) {
            float4 a = *(const float4*)(u + row*N2 + cb);
            dst[0] = make_float2(a.x, a.y);
            dst[1] = make_float2(a.z, a.w);
        } else {
            dst[0] = (cb     < N2) ? u[row*N2 + cb]     : make_float2(0.f, 0.f);
            dst[1] = (cb + 1 < N2) ? u[row*N2 + cb + 1] : make_float2(0.f, 0.f);
        }
    }
    __syncthreads();

    float2 v[8];
#pragma unroll
    for (int r = 0; r < 8; r++) v[r] = stage[(j + (r << 6))*8 + c];
    __syncthreads();
    bfly8<true>(v);
#pragma unroll
    for (int r = 0; r < 8; r++) smA[c][j*8 + r] = v[r];
    __syncthreads();
    {
#pragma unroll
        for (int r = 0; r < 8; r++) v[r] = smA[c][j + 64*r];
        int m = j & 7;
        tw8(6.2831853071795864f/64.f * (float)m, v);
        bfly8<true>(v);
        int db = (j >> 3)*64 + m;
#pragma unroll
        for (int r = 0; r < 8; r++) smB[c][db + 8*r] = v[r];
    }
    __syncthreads();
    {
#pragma unroll
        for (int r = 0; r < 8; r++) v[r] = smB[c][j + 64*r];
        tw8(6.2831853071795864f/512.f * (float)j, v);
        bfly8<true>(v);
        if (val) {
            const float sc = 1.f/256000.f;
            float* o0 = out + 2*s*NSMP;
            float* o1 = out + (2*s+1)*NSMP;
#pragma unroll
            for (int r = 0; r < 8; r++) {
                int idx = (j + 64*r)*N2 + n2;
                o0[idx] = v[r].x * sc;
                o1[idx] = v[r].y * sc;
            }
        }
    }
}

// ---------------- launch (forked prologue + PDL chain) ----------------
extern "C" void kernel_launch(void* const* d_in, const int* in_sizes, int n_in,
                              void* d_out, int out_size) {
    const float* mag;
    const float* noise;
    if (in_sizes[0] == NBATCH*NFR*NBK) { mag = (const float*)d_in[0]; noise = (const float*)d_in[1]; }
    else                               { mag = (const float*)d_in[1]; noise = (const float*)d_in[0]; }
    float* out = (float*)d_out;

    static cudaStream_t s1 = nullptr;
    static cudaEvent_t evFork = nullptr, evJoin = nullptr;
    if (!s1) {
        cudaStreamCreateWithFlags(&s1, cudaStreamNonBlocking);
        cudaEventCreateWithFlags(&evFork, cudaEventDisableTiming);
        cudaEventCreateWithFlags(&evJoin, cudaEventDisableTiming);
    }

    cudaLaunchAttribute pdl[1];
    pdl[0].id = cudaLaunchAttributeProgrammaticStreamSerialization;
    pdl[0].val.programmaticStreamSerializationAllowed = 1;

    // fork: prologue (mean-mag + dual-write transposed filter table) overlaps p1f
    cudaEventRecord(evFork, 0);
    cudaStreamWaitEvent(s1, evFork, 0);
    k_mm_part<<<dim3(NCH, NBATCH), 64, 0, s1>>>(mag);
    {
        cudaLaunchConfig_t cfg = {};
        cfg.gridDim = dim3((NFQ + 127)/128);
        cfg.blockDim = dim3(128);
        cfg.stream = s1;
        cfg.attrs = pdl;
        cfg.numAttrs = 1;
        cudaLaunchKernelEx(&cfg, k_filter_Ht);
    }
    cudaEventRecord(evJoin, s1);

    k_p1f<<<dim3(63, 2), 512>>>(noise);

    // join: pMid needs g_Ht2
    cudaStreamWaitEvent(0, evJoin, 0);

    {
        cudaLaunchConfig_t cfg = {};
        cfg.gridDim = dim3(256, 2);
        cfg.blockDim = dim3(256);
        cfg.attrs = pdl;
        cfg.numAttrs = 1;
        cudaLaunchKernelEx(&cfg, k_pMid);
    }
    {
        cudaLaunchConfig_t cfg = {};
        cfg.gridDim = dim3(63, 2);
        cfg.blockDim = dim3(512);
        cfg.attrs = pdl;
        cfg.numAttrs = 1;
        cudaLaunchKernelEx(&cfg, k_pBi, out);
    }
}

// round 16
// speedup vs baseline: 1.0656x; 1.0656x over previous
#include <cuda_runtime.h>
#include <math.h>

#define NSMP   256000        // = 512 * 500
#define N1     512
#define N2     500
#define NBATCH 4
#define NFR    500
#define NBK    64
#define NFQ    128001
#define NCH    10
#define CHF    50

// ---------------- scratch ----------------
__device__ float2 g_u[2][N1 * N2];      // 4 MB working buffer
__device__ float2 g_Ht2[2][N1 * N2];    // transposed filter, paired: [s][k1*500+k2] = {H[2s],H[2s+1]}
__device__ float  g_part[NCH][NBATCH][NBK];

// ---------------- helpers ----------------
__device__ __forceinline__ float2 c_add(float2 a, float2 b){ return make_float2(a.x+b.x, a.y+b.y); }
__device__ __forceinline__ float2 c_sub(float2 a, float2 b){ return make_float2(a.x-b.x, a.y-b.y); }
__device__ __forceinline__ float2 cxm(float2 a, float2 b){
    return make_float2(a.x*b.x - a.y*b.y, a.x*b.y + a.y*b.x);
}

template<int R, bool INV>
__device__ __forceinline__ void butterfly(float2* v) {
    const float s = INV ? 1.f : -1.f;
    if constexpr (R == 4) {
        float2 t0 = c_add(v[0], v[2]), t1 = c_sub(v[0], v[2]);
        float2 t2 = c_add(v[1], v[3]), t3 = c_sub(v[1], v[3]);
        float2 it3 = make_float2(-s * t3.y, s * t3.x);
        v[0] = c_add(t0, t2); v[2] = c_sub(t0, t2);
        v[1] = c_add(t1, it3); v[3] = c_sub(t1, it3);
    } else if constexpr (R == 5) {
        const float c1 = 0.30901699437494742f, c2 = -0.80901699437494745f;
        const float s1 = 0.95105651629515357f, s2 =  0.58778525229247312f;
        float2 t1 = c_add(v[1], v[4]), t2 = c_add(v[2], v[3]);
        float2 t3 = c_sub(v[1], v[4]), t4 = c_sub(v[2], v[3]);
        float2 x0 = v[0];
        float2 m1 = make_float2(x0.x + c1*t1.x + c2*t2.x, x0.y + c1*t1.y + c2*t2.y);
        float2 m2 = make_float2(x0.x + c2*t1.x + c1*t2.x, x0.y + c2*t1.y + c1*t2.y);
        float2 u1 = make_float2(s1*t3.x + s2*t4.x, s1*t3.y + s2*t4.y);
        float2 u2 = make_float2(s2*t3.x - s1*t4.x, s2*t3.y - s1*t4.y);
        float2 iu1 = make_float2(-s*u1.y, s*u1.x);
        float2 iu2 = make_float2(-s*u2.y, s*u2.x);
        v[0] = make_float2(x0.x + t1.x + t2.x, x0.y + t1.y + t2.y);
        v[1] = c_add(m1, iu1); v[4] = c_sub(m1, iu1);
        v[2] = c_add(m2, iu2); v[3] = c_sub(m2, iu2);
    }
}

template<bool INV>
__device__ __forceinline__ void bfly8(float2* v) {
    float2 u0[4] = { v[0], v[2], v[4], v[6] };
    float2 u1[4] = { v[1], v[3], v[5], v[7] };
    butterfly<4, INV>(u0);
    butterfly<4, INV>(u1);
    const float h  = 0.70710678118654752f;
    const float si = INV ? 1.f : -1.f;
    float2 t0 = u1[0];
    float2 t1 = make_float2(h*(u1[1].x - si*u1[1].y), h*(si*u1[1].x + u1[1].y));
    float2 t2 = make_float2(-si*u1[2].y, si*u1[2].x);
    float2 t3 = make_float2(h*(-u1[3].x - si*u1[3].y), h*(si*u1[3].x - u1[3].y));
    v[0] = c_add(u0[0], t0); v[4] = c_sub(u0[0], t0);
    v[1] = c_add(u0[1], t1); v[5] = c_sub(u0[1], t1);
    v[2] = c_add(u0[2], t2); v[6] = c_sub(u0[2], t2);
    v[3] = c_add(u0[3], t3); v[7] = c_sub(u0[3], t3);
}

// one sincosf + power chain: multiply v[1..4] by w^r
__device__ __forceinline__ void tw5(float base, float2* v) {
    float sn, cs; __sincosf(base, &sn, &cs);
    float2 w1 = make_float2(cs, sn);
    float2 w2 = cxm(w1, w1);
    float2 w3 = cxm(w2, w1);
    float2 w4 = cxm(w2, w2);
    v[1] = cxm(v[1], w1); v[2] = cxm(v[2], w2);
    v[3] = cxm(v[3], w3); v[4] = cxm(v[4], w4);
}

// one sincosf + power chain: multiply v[1..7] by w^r
__device__ __forceinline__ void tw8(float base, float2* v) {
    float sn, cs; __sincosf(base, &sn, &cs);
    float2 w1 = make_float2(cs, sn);
    float2 w2 = cxm(w1, w1);
    float2 w3 = cxm(w2, w1);
    float2 w4 = cxm(w2, w2);
    float2 w5 = cxm(w4, w1);
    float2 w6 = cxm(w3, w3);
    float2 w7 = cxm(w3, w4);
    v[1] = cxm(v[1], w1); v[2] = cxm(v[2], w2); v[3] = cxm(v[3], w3);
    v[4] = cxm(v[4], w4); v[5] = cxm(v[5], w5); v[6] = cxm(v[6], w6);
    v[7] = cxm(v[7], w7);
}

// radix-5 Stockham stage body (caller guards t<100)
template<bool INV>
__device__ __forceinline__ void stage5(const float2* __restrict__ src, float2* __restrict__ dst,
                                       int t, int m, int Ns, float base) {
    float2 v[5];
#pragma unroll
    for (int r = 0; r < 5; r++) v[r] = src[t + 100*r];
    tw5(base, v);
    butterfly<5, INV>(v);
    int db = (t/Ns)*(Ns*5) + m;
#pragma unroll
    for (int r = 0; r < 5; r++) dst[db + Ns*r] = v[r];
}

#define BROW() asm volatile("bar.sync %0, 128;" :: "r"(half + 1) : "memory")

// ---------------- partial mean-magnitude (closed-form frame weights) ----------------
__global__ void k_mm_part(const float* __restrict__ mag) {
    int c = blockIdx.x, b = blockIdx.y;
    int t = threadIdx.x;    // 64
    __shared__ float sw[CHF];
    if (t < CHF) {
        int f = c*CHF + t;
        const double s = 499.0/255999.0;
        long long a1 = ((long long)f*255999LL + 498LL)/499LL;
        long long b1 = ((long long)(f+1)*255999LL + 498LL)/499LL - 1LL;
        if (b1 > 255999LL) b1 = 255999LL;
        double cnt1 = (double)(b1 - a1 + 1);
        double si1  = 0.5*(double)(a1 + b1)*cnt1;
        double sum  = cnt1*(double)(1 + f) - s*si1;
        if (f >= 1) {
            long long a2 = ((long long)(f-1)*255999LL + 498LL)/499LL;
            long long b2 = a1 - 1LL;
            if (b2 >= a2) {
                double cnt2 = (double)(b2 - a2 + 1);
                double si2  = 0.5*(double)(a2 + b2)*cnt2;
                sum += s*si2 - (double)(f-1)*cnt2;
            }
        }
        sw[t] = (float)(sum/256000.0);
    }
    __syncthreads();
    float acc = 0.f;
    const float* mp = mag + (b*NFR + c*CHF)*NBK + t;
#pragma unroll 10
    for (int f = 0; f < CHF; f++) acc += sw[f]*mp[f*NBK];
    g_part[c][b][t] = acc;
}

// ---------------- filter response over frequencies, dual scatter-write to transposed table ----------------
__global__ void __launch_bounds__(128) k_filter_Ht() {
    // PDL: overlap launch with k_mm_part tail; block before reading g_part
    cudaGridDependencySynchronize();

    __shared__ float smm[NBATCH*NBK];
    int t = threadIdx.x;
    for (int i = t; i < NBATCH*NBK; i += 128) {
        float a = 0.f;
        const float* p = (const float*)g_part;
#pragma unroll
        for (int c = 0; c < NCH; c++) a += p[c*256 + i];
        smm[i] = a;
    }
    __syncthreads();

    int f = blockIdx.x*128 + t;
    if (f >= NFQ) return;

    const float la = 2.9957322735539909f;          // ln(20)
    const float d  = 0.10019346708895288f;         // (ln(11025)-ln(20))/63
    const float C2 = 0.98012272f;                  // exp(-2 d^2)
    const float C8 = 0.92283040f;                  // exp(-8 d^2)
    const float G4 = 0.85161593f;                  // exp(-16 d^2)

    float freq = (float)f * (22050.0f/256000.0f);
    float xp = __logf(freq + 1e-7f) - la;

    float te = __expf(-2.f*xp*xp);
    float E  = __expf(4.f*d*xp);
    float to = te*E*C2;
    float E2 = E*E;
    float Re = E2*C8;
    float Ro = Re*C8;

    float sum = 0.f, a0 = 0.f, a1 = 0.f, a2 = 0.f, a3 = 0.f;
#pragma unroll
    for (int q = 0; q < 64; q += 2) {
        sum += te + to;
        a0 += te*smm[q]       + to*smm[q+1];
        a1 += te*smm[64+q]    + to*smm[65+q];
        a2 += te*smm[128+q]   + to*smm[129+q];
        a3 += te*smm[192+q]   + to*smm[193+q];
        te *= Re; Re *= G4;
        to *= Ro; Ro *= G4;
    }
    float inv = 1.f/(sum + 1e-7f);
    float2 h01 = make_float2(a0*inv, a1*inv);
    float2 h23 = make_float2(a2*inv, a3*inv);

    int idxA = (f & 511)*N2 + (f >> 9);
    g_Ht2[0][idxA] = h01;
    g_Ht2[1][idxA] = h23;
    if (f > 0 && f < 128000) {
        int kb = 256000 - f;
        int idxB = (kb & 511)*N2 + (kb >> 9);
        g_Ht2[0][idxB] = h01;
        g_Ht2[1][idxB] = h23;
    }
}

// ---------------- pass 1: FFT-512 per column + cross twiddle (ping-pong smem, 2 barriers) ----------------
__global__ void __launch_bounds__(512) k_p1f(const float* __restrict__ noise) {
    __shared__ float2 smA[8][516];
    __shared__ float2 smB[8][516];
    int tid = threadIdx.x;
    int c = tid & 7, j = tid >> 3;          // j in [0,64)
    int n2 = blockIdx.x*8 + c;
    bool val = (n2 < N2);
    int s = blockIdx.y;
    const float* n0r = noise + 2*s*NSMP;
    const float* n1r = noise + (2*s+1)*NSMP;

    float2 v[8];
    if (val) {
#pragma unroll
        for (int r = 0; r < 8; r++) {
            int idx = (j + 64*r)*N2 + n2;
            v[r] = make_float2(n0r[idx], n1r[idx]);
        }
    } else {
#pragma unroll
        for (int r = 0; r < 8; r++) v[r] = make_float2(0.f, 0.f);
    }
    bfly8<false>(v);
#pragma unroll
    for (int r = 0; r < 8; r++) smA[c][j*8 + r] = v[r];
    __syncthreads();
    {
#pragma unroll
        for (int r = 0; r < 8; r++) v[r] = smA[c][j + 64*r];
        int m = j & 7;
        tw8(-6.2831853071795864f/64.f * (float)m, v);
        bfly8<false>(v);
        int db = (j >> 3)*64 + m;
#pragma unroll
        for (int r = 0; r < 8; r++) smB[c][db + 8*r] = v[r];
    }
    __syncthreads();
    {
#pragma unroll
        for (int r = 0; r < 8; r++) v[r] = smB[c][j + 64*r];
        tw8(-6.2831853071795864f/512.f * (float)j, v);
        bfly8<false>(v);
        if (val) {
            float cb = -6.2831853071795864f/256000.f * (float)n2;
            float snj, csj; __sincosf(cb*(float)j, &snj, &csj);
            float snW, csW; __sincosf(cb*64.f, &snW, &csW);
            float2 wk = make_float2(csj, snj);
            float2 W  = make_float2(csW, snW);
            float2* u = g_u[s];
#pragma unroll
            for (int r = 0; r < 8; r++) {
                int k1 = j + 64*r;
                u[k1*N2 + n2] = cxm(v[r], wk);
                wk = cxm(wk, W);
            }
        }
    }
}

// ---------------- fused middle: fwd FFT-500 + spectral filter (coalesced Ht2) + inv FFT-500 ----------------
__global__ void __launch_bounds__(256) k_pMid() {
    __shared__ float2 sA[2][N2], sB[2][N2];
    int tid = threadIdx.x;
    int half = tid >> 7, t = tid & 127;
    int p = blockIdx.x;                  // 0..255
    int s = blockIdx.y;
    int ra = (p == 0) ? 0   : p;
    int rb = (p == 0) ? 256 : 512 - p;
    int myrow = half ? rb : ra;
    float2* A = sA[half];
    float2* B = sB[half];

    // PDL: overlap launch with p1f tail; block before first dependent read
    cudaGridDependencySynchronize();

    // fwd s1: radix-4, Ns=1 — read g_u directly
    {
        const float2* src = g_u[s] + myrow*N2;
        if (t < 125) {
            float2 v[4];
#pragma unroll
            for (int r = 0; r < 4; r++) v[r] = src[t + 125*r];
            butterfly<4, false>(v);
#pragma unroll
            for (int r = 0; r < 4; r++) A[t*4 + r] = v[r];
        }
    }
    BROW();
    if (t < 100) stage5<false>(A, B, t, t & 3,  4,  -6.2831853071795864f/20.f  * (float)(t & 3));
    BROW();
    if (t < 100) stage5<false>(B, A, t, t % 20, 20, -6.2831853071795864f/100.f * (float)(t % 20));
    BROW();
    if (t < 100) stage5<false>(A, B, t, t,      100,-6.2831853071795864f/500.f * (float)t);
    __syncthreads();    // spectrum in sB (both halves)

    // spectral filter fused into inverse s1 (radix-4, Ns=1): sB -> sA
    {
        const float2* Hp = g_Ht2[s] + myrow*N2;   // coalesced: adjacent lanes adjacent k2
        if (t < 125) {
            float2 v[4];
#pragma unroll
            for (int r = 0; r < 4; r++) {
                int k2 = t + 125*r;
                float2 zk = B[k2];
                float2 zn;
                if (p == 0) {
                    if (!half) zn = sB[0][k2 ? N2 - k2 : 0];
                    else       zn = sB[1][N2 - 1 - k2];
                } else {
                    zn = sB[1 - half][N2 - 1 - k2];
                }
                float2 h = Hp[k2];
                float X0r = 0.5f*(zk.x + zn.x), X0i = 0.5f*(zk.y - zn.y);
                float X1r = 0.5f*(zk.y + zn.y), X1i = -0.5f*(zk.x - zn.x);
                v[r] = make_float2(h.x*X0r - h.y*X1i, h.x*X0i + h.y*X1r);
            }
            butterfly<4, true>(v);
#pragma unroll
            for (int r = 0; r < 4; r++) A[t*4 + r] = v[r];
        }
    }
    __syncthreads();    // cross-half sB reads must finish before inv writes sB

    if (t < 100) stage5<true>(A, B, t, t & 3,  4,  6.2831853071795864f/20.f  * (float)(t & 3));
    BROW();
    if (t < 100) stage5<true>(B, A, t, t % 20, 20, 6.2831853071795864f/100.f * (float)(t % 20));
    BROW();
    // inv s4 (Ns=100) fused with cross-twiddle + store
    if (t < 100) {
        float2 v[5];
#pragma unroll
        for (int r = 0; r < 5; r++) v[r] = A[t + 100*r];
        tw5(6.2831853071795864f/500.f * (float)t, v);
        butterfly<5, true>(v);
        float cb = 6.2831853071795864f/256000.f * (float)myrow;
        float snt, cst; __sincosf(cb*(float)t,   &snt, &cst);
        float snW, csW; __sincosf(cb*100.f,      &snW, &csW);
        float2 wk = make_float2(cst, snt);
        float2 W  = make_float2(csW, snW);
        float2* dst = g_u[s] + myrow*N2;
#pragma unroll
        for (int r = 0; r < 5; r++) {
            dst[t + 100*r] = cxm(v[r], wk);
            wk = cxm(wk, W);
        }
    }
}

// ---------------- pass B: iFFT-512 per column + scale + unpack (ping-pong smem) ----------------
__global__ void __launch_bounds__(512) k_pBi(float* __restrict__ out) {
    __shared__ float2 smA[8][516];
    __shared__ float2 smB[8][516];
    int tid = threadIdx.x;
    int c = tid & 7, j = tid >> 3;
    int n2 = blockIdx.x*8 + c;
    bool val = (n2 < N2);
    int s = blockIdx.y;
    const float2* u = g_u[s];

    // PDL: overlap launch with pMid tail; block before first dependent read
    cudaGridDependencySynchronize();

    float2 v[8];
    if (val) {
#pragma unroll
        for (int r = 0; r < 8; r++) v[r] = u[(j + 64*r)*N2 + n2];
    } else {
#pragma unroll
        for (int r = 0; r < 8; r++) v[r] = make_float2(0.f, 0.f);
    }
    bfly8<true>(v);
#pragma unroll
    for (int r = 0; r < 8; r++) smA[c][j*8 + r] = v[r];
    __syncthreads();
    {
#pragma unroll
        for (int r = 0; r < 8; r++) v[r] = smA[c][j + 64*r];
        int m = j & 7;
        tw8(6.2831853071795864f/64.f * (float)m, v);
        bfly8<true>(v);
        int db = (j >> 3)*64 + m;
#pragma unroll
        for (int r = 0; r < 8; r++) smB[c][db + 8*r] = v[r];
    }
    __syncthreads();
    {
#pragma unroll
        for (int r = 0; r < 8; r++) v[r] = smB[c][j + 64*r];
        tw8(6.2831853071795864f/512.f * (float)j, v);
        bfly8<true>(v);
        if (val) {
            const float sc = 1.f/256000.f;
            float* o0 = out + 2*s*NSMP;
            float* o1 = out + (2*s+1)*NSMP;
#pragma unroll
            for (int r = 0; r < 8; r++) {
                int idx = (j + 64*r)*N2 + n2;
                o0[idx] = v[r].x * sc;
                o1[idx] = v[r].y * sc;
            }
        }
    }
}

// ---------------- launch (forked prologue + PDL chain) ----------------
extern "C" void kernel_launch(void* const* d_in, const int* in_sizes, int n_in,
                              void* d_out, int out_size) {
    const float* mag;
    const float* noise;
    if (in_sizes[0] == NBATCH*NFR*NBK) { mag = (const float*)d_in[0]; noise = (const float*)d_in[1]; }
    else                               { mag = (const float*)d_in[1]; noise = (const float*)d_in[0]; }
    float* out = (float*)d_out;

    static cudaStream_t s1 = nullptr;
    static cudaEvent_t evFork = nullptr, evJoin = nullptr;
    if (!s1) {
        cudaStreamCreateWithFlags(&s1, cudaStreamNonBlocking);
        cudaEventCreateWithFlags(&evFork, cudaEventDisableTiming);
        cudaEventCreateWithFlags(&evJoin, cudaEventDisableTiming);
    }

    cudaLaunchAttribute pdl[1];
    pdl[0].id = cudaLaunchAttributeProgrammaticStreamSerialization;
    pdl[0].val.programmaticStreamSerializationAllowed = 1;

    // fork: prologue (mean-mag + dual-write transposed filter table) overlaps p1f
    cudaEventRecord(evFork, 0);
    cudaStreamWaitEvent(s1, evFork, 0);
    k_mm_part<<<dim3(NCH, NBATCH), 64, 0, s1>>>(mag);
    {
        cudaLaunchConfig_t cfg = {};
        cfg.gridDim = dim3((NFQ + 127)/128);
        cfg.blockDim = dim3(128);
        cfg.stream = s1;
        cfg.attrs = pdl;
        cfg.numAttrs = 1;
        cudaLaunchKernelEx(&cfg, k_filter_Ht);
    }
    cudaEventRecord(evJoin, s1);

    k_p1f<<<dim3(63, 2), 512>>>(noise);

    // join: pMid needs g_Ht2
    cudaStreamWaitEvent(0, evJoin, 0);

    {
        cudaLaunchConfig_t cfg = {};
        cfg.gridDim = dim3(256, 2);
        cfg.blockDim = dim3(256);
        cfg.attrs = pdl;
        cfg.numAttrs = 1;
        cudaLaunchKernelEx(&cfg, k_pMid);
    }
    {
        cudaLaunchConfig_t cfg = {};
        cfg.gridDim = dim3(63, 2);
        cfg.blockDim = dim3(512);
        cfg.attrs = pdl;
        cfg.numAttrs = 1;
        cudaLaunchKernelEx(&cfg, k_pBi, out);
    }
}